// round 1
// baseline (speedup 1.0000x reference)
#include <cuda_runtime.h>

#define NM   8192
#define DIMM 256
#define NH   8
#define EE   32
#define MB   16
#define NB   512
#define NKEY 32   // TOPK * MB

// ---------------- scratch (device globals; no allocation allowed) ----------
__device__ float g_xp[NM * DIMM];        // x + positional encoding
__device__ float g_q[NH * NM * EE];      // [H][token][E]
__device__ float g_k[NH * NM * EE];      // [H][token][E]  (token = ball*16+m)
__device__ float g_v[NH * NM * EE];
__device__ float g_kmean[NH * NB * EE];  // [H][ball][E]
__device__ int   g_idx[NH * NM * 2];     // top-2 ball ids per (h, token)
__device__ float g_ao[NM * DIMM];        // attention output, token-major

// ---------------- k1: relative-position encoding add ----------------------
// one block per ball (16 tokens), 256 threads = one per feature dim
__global__ void k1_pe(const float* __restrict__ x, const float* __restrict__ pos,
                      const float* __restrict__ Wpe, const float* __restrict__ bpe) {
    int ball = blockIdx.x;
    int tid  = threadIdx.x;
    __shared__ float rel[MB][3];
    if (tid < 3) {
        float s = 0.f;
        for (int m = 0; m < MB; m++) s += pos[(ball * MB + m) * 3 + tid];
        float mean = s * (1.f / MB);
        for (int m = 0; m < MB; m++)
            rel[m][tid] = pos[(ball * MB + m) * 3 + tid] - mean;
    }
    __syncthreads();
    int d = tid;
    float w0 = Wpe[d * 3 + 0], w1 = Wpe[d * 3 + 1], w2 = Wpe[d * 3 + 2];
    float b  = bpe[d];
    #pragma unroll
    for (int m = 0; m < MB; m++) {
        int t = ball * MB + m;
        g_xp[t * DIMM + d] = x[t * DIMM + d]
                           + rel[m][0] * w0 + rel[m][1] * w1 + rel[m][2] * w2 + b;
    }
}

// ---------------- k2: QKV GEMM (NT) + scatter into q/k/v -------------------
// C[8192,768] = g_xp[8192,256] @ W_qkv[768,256]^T ; 64x64 tile, 4x4/thread
__global__ void k2_qkv(const float* __restrict__ W, const float* __restrict__ bias) {
    __shared__ float As[16][65];
    __shared__ float Bs[16][65];
    int tid = threadIdx.x;
    int tx = tid & 15, ty = tid >> 4;
    int row0 = blockIdx.x * 64, col0 = blockIdx.y * 64;
    float acc[4][4] = {};
    for (int k0 = 0; k0 < DIMM; k0 += 16) {
        #pragma unroll
        for (int l = 0; l < 4; l++) {
            int e = tid + l * 256;
            int r = e >> 4, kk = e & 15;
            As[kk][r] = g_xp[(row0 + r) * DIMM + k0 + kk];
            Bs[kk][r] = W[(col0 + r) * DIMM + k0 + kk];
        }
        __syncthreads();
        #pragma unroll
        for (int kk = 0; kk < 16; kk++) {
            float a[4], b[4];
            #pragma unroll
            for (int i = 0; i < 4; i++) a[i] = As[kk][ty + 16 * i];
            #pragma unroll
            for (int j = 0; j < 4; j++) b[j] = Bs[kk][tx + 16 * j];
            #pragma unroll
            for (int i = 0; i < 4; i++)
                #pragma unroll
                for (int j = 0; j < 4; j++) acc[i][j] += a[i] * b[j];
        }
        __syncthreads();
    }
    #pragma unroll
    for (int i = 0; i < 4; i++) {
        #pragma unroll
        for (int j = 0; j < 4; j++) {
            int r = row0 + ty + 16 * i;          // token
            int c = col0 + tx + 16 * j;          // qkv column 0..767
            float v = acc[i][j] + bias[c];
            int h = c / 96, t = c % 96;
            int e = t / 3, s = t - e * 3;        // s: 0=q 1=k 2=v (innermost)
            float* dst = (s == 0) ? g_q : (s == 1) ? g_k : g_v;
            dst[(h * NM + r) * EE + e] = v;
        }
    }
}

// ---------------- k3: per-ball key means -----------------------------------
__global__ void k3_kmean() {
    int t = blockIdx.x * blockDim.x + threadIdx.x;   // NH*NB*EE = 131072
    int e = t & 31;
    int ball = (t >> 5) & (NB - 1);
    int h = t >> 14;
    const float* base = g_k + (h * NM + ball * MB) * EE + e;
    float s = 0.f;
    #pragma unroll
    for (int m = 0; m < MB; m++) s += base[m * EE];
    g_kmean[t] = s * (1.f / MB);
}

// ---------------- k4: sim = q . kmean over 512 balls, keep top-2 ----------
// one thread per (h, token)
__global__ void k4_top2() {
    int t = blockIdx.x * blockDim.x + threadIdx.x;   // NH*NM = 65536
    int h = t >> 13;
    int tok = t & (NM - 1);
    float q[EE];
    const float* qr = g_q + (h * NM + tok) * EE;
    #pragma unroll
    for (int e = 0; e < EE; e++) q[e] = qr[e];
    float v1 = -1e30f, v2 = -1e30f;
    int i1 = 0, i2 = 0;
    const float* km = g_kmean + h * NB * EE;
    for (int b = 0; b < NB; b++) {
        float s = 0.f;
        #pragma unroll
        for (int e = 0; e < EE; e++) s += q[e] * km[b * EE + e];
        if (s > v1) { v2 = v1; i2 = i1; v1 = s; i1 = b; }
        else if (s > v2) { v2 = s; i2 = b; }
    }
    g_idx[t * 2 + 0] = i1;
    g_idx[t * 2 + 1] = i2;
}

// ---------------- k5: gathered 32-key attention ----------------------------
// one warp per (h, token); lane = key index, then lane = output dim
__global__ void k5_attn() {
    int warp = (blockIdx.x * blockDim.x + threadIdx.x) >> 5;  // 65536 warps
    int lane = threadIdx.x & 31;
    int h = warp >> 13;
    int tok = warp & (NM - 1);
    int b0 = g_idx[warp * 2 + 0];
    int b1 = g_idx[warp * 2 + 1];

    // phase 1: lane = key index kk in [0,32)
    int ball = (lane < 16) ? b0 : b1;
    int ktok = ball * MB + (lane & 15);
    const float* krow = g_k + (h * NM + ktok) * EE;
    const float* qrow = g_q + (h * NM + tok) * EE;
    float logit = 0.f;
    #pragma unroll
    for (int e = 0; e < EE; e++) logit += qrow[e] * krow[e];
    logit *= 0.17677669529663688f;  // 1/sqrt(32)

    // warp softmax over 32 logits
    float m = logit;
    #pragma unroll
    for (int off = 16; off > 0; off >>= 1)
        m = fmaxf(m, __shfl_xor_sync(0xffffffffu, m, off));
    float p = __expf(logit - m);
    float s = p;
    #pragma unroll
    for (int off = 16; off > 0; off >>= 1)
        s += __shfl_xor_sync(0xffffffffu, s, off);
    float attn = p / s;

    // phase 2: lane = output dim e; out[e] = sum_kk attn_kk * v[key_kk][e]
    float out = 0.f;
    #pragma unroll
    for (int kk = 0; kk < NKEY; kk++) {
        float a = __shfl_sync(0xffffffffu, attn, kk);
        int kt = ((kk < 16) ? b0 : b1) * MB + (kk & 15);
        out += a * g_v[(h * NM + kt) * EE + lane];
    }
    g_ao[tok * DIMM + h * EE + lane] = out;
}

// ---------------- k6: output projection GEMM (NT) --------------------------
// out[8192,256] = g_ao[8192,256] @ W_proj[256,256]^T + b
__global__ void k6_proj(const float* __restrict__ W, const float* __restrict__ bias,
                        float* __restrict__ out) {
    __shared__ float As[16][65];
    __shared__ float Bs[16][65];
    int tid = threadIdx.x;
    int tx = tid & 15, ty = tid >> 4;
    int row0 = blockIdx.x * 64, col0 = blockIdx.y * 64;
    float acc[4][4] = {};
    for (int k0 = 0; k0 < DIMM; k0 += 16) {
        #pragma unroll
        for (int l = 0; l < 4; l++) {
            int e = tid + l * 256;
            int r = e >> 4, kk = e & 15;
            As[kk][r] = g_ao[(row0 + r) * DIMM + k0 + kk];
            Bs[kk][r] = W[(col0 + r) * DIMM + k0 + kk];
        }
        __syncthreads();
        #pragma unroll
        for (int kk = 0; kk < 16; kk++) {
            float a[4], b[4];
            #pragma unroll
            for (int i = 0; i < 4; i++) a[i] = As[kk][ty + 16 * i];
            #pragma unroll
            for (int j = 0; j < 4; j++) b[j] = Bs[kk][tx + 16 * j];
            #pragma unroll
            for (int i = 0; i < 4; i++)
                #pragma unroll
                for (int j = 0; j < 4; j++) acc[i][j] += a[i] * b[j];
        }
        __syncthreads();
    }
    #pragma unroll
    for (int i = 0; i < 4; i++) {
        #pragma unroll
        for (int j = 0; j < 4; j++) {
            int r = row0 + ty + 16 * i;
            int c = col0 + tx + 16 * j;
            out[r * DIMM + c] = acc[i][j] + bias[c];
        }
    }
}

// ---------------- launch ----------------------------------------------------
extern "C" void kernel_launch(void* const* d_in, const int* in_sizes, int n_in,
                              void* d_out, int out_size) {
    const float* x     = (const float*)d_in[0];
    const float* pos   = (const float*)d_in[1];
    const float* Wqkv  = (const float*)d_in[2];
    const float* bqkv  = (const float*)d_in[3];
    const float* Wpe   = (const float*)d_in[4];
    const float* bpe   = (const float*)d_in[5];
    const float* Wproj = (const float*)d_in[6];
    const float* bproj = (const float*)d_in[7];
    float* out = (float*)d_out;

    k1_pe<<<NB, 256>>>(x, pos, Wpe, bpe);
    k2_qkv<<<dim3(NM / 64, 768 / 64), 256>>>(Wqkv, bqkv);
    k3_kmean<<<(NH * NB * EE) / 256, 256>>>();
    k4_top2<<<(NH * NM) / 256, 256>>>();
    k5_attn<<<(NH * NM * 32) / 256, 256>>>();
    k6_proj<<<dim3(NM / 64, DIMM / 64), 256>>>(Wproj, bproj, out);
}

// round 2
// speedup vs baseline: 2.2412x; 2.2412x over previous
#include <cuda_runtime.h>

#define NM   8192
#define DIMM 256
#define NH   8
#define EE   32
#define MB   16
#define NB   512
#define NKEY 32

// ---------------- scratch ----------------------------------------------------
__device__ float g_xp[NM * DIMM];
__device__ float g_q[NH * NM * EE];
__device__ float g_k[NH * NM * EE];
__device__ float g_v[NH * NM * EE];
__device__ float g_kmean[NH * NB * EE];
__device__ int   g_idx[NH * NM * 2];
__device__ float g_ao[NM * DIMM];

// ---------------- k1: relative-position encoding add ------------------------
__global__ void k1_pe(const float* __restrict__ x, const float* __restrict__ pos,
                      const float* __restrict__ Wpe, const float* __restrict__ bpe) {
    int ball = blockIdx.x;
    int tid  = threadIdx.x;
    __shared__ float rel[MB][3];
    if (tid < 3) {
        float s = 0.f;
        for (int m = 0; m < MB; m++) s += pos[(ball * MB + m) * 3 + tid];
        float mean = s * (1.f / MB);
        for (int m = 0; m < MB; m++)
            rel[m][tid] = pos[(ball * MB + m) * 3 + tid] - mean;
    }
    __syncthreads();
    int d = tid;
    float w0 = Wpe[d * 3 + 0], w1 = Wpe[d * 3 + 1], w2 = Wpe[d * 3 + 2];
    float b  = bpe[d];
    #pragma unroll
    for (int m = 0; m < MB; m++) {
        int t = ball * MB + m;
        g_xp[t * DIMM + d] = x[t * DIMM + d]
                           + rel[m][0] * w0 + rel[m][1] * w1 + rel[m][2] * w2 + b;
    }
}

// ---------------- shared 128x128x16 fp32 GEMM-NT body -----------------------
// C[M,N] = A[M,256] * B[N,256]^T. 256 threads, 8x8 accum per thread.
// As/Bs stored k-major: As[kk][r].
#define GEMM_TILE_LOAD(Aptr, Bptr)                                              \
    {                                                                           \
        int r  = tid & 127;                                                     \
        int k8 = (tid >> 7) * 8;                                                \
        float4 a0 = *(const float4*)(Aptr + (row0 + r) * DIMM + k0 + k8);       \
        float4 a1 = *(const float4*)(Aptr + (row0 + r) * DIMM + k0 + k8 + 4);   \
        float4 b0 = *(const float4*)(Bptr + (col0 + r) * DIMM + k0 + k8);       \
        float4 b1 = *(const float4*)(Bptr + (col0 + r) * DIMM + k0 + k8 + 4);   \
        As[(k8 + 0) * 132 + r] = a0.x; As[(k8 + 1) * 132 + r] = a0.y;           \
        As[(k8 + 2) * 132 + r] = a0.z; As[(k8 + 3) * 132 + r] = a0.w;           \
        As[(k8 + 4) * 132 + r] = a1.x; As[(k8 + 5) * 132 + r] = a1.y;           \
        As[(k8 + 6) * 132 + r] = a1.z; As[(k8 + 7) * 132 + r] = a1.w;           \
        Bs[(k8 + 0) * 132 + r] = b0.x; Bs[(k8 + 1) * 132 + r] = b0.y;           \
        Bs[(k8 + 2) * 132 + r] = b0.z; Bs[(k8 + 3) * 132 + r] = b0.w;           \
        Bs[(k8 + 4) * 132 + r] = b1.x; Bs[(k8 + 5) * 132 + r] = b1.y;           \
        Bs[(k8 + 6) * 132 + r] = b1.z; Bs[(k8 + 7) * 132 + r] = b1.w;           \
    }

#define GEMM_MAIN(acc)                                                          \
    _Pragma("unroll")                                                           \
    for (int kk = 0; kk < 16; kk++) {                                           \
        float4 a0 = *(const float4*)(As + kk * 132 + ty * 4);                   \
        float4 a1 = *(const float4*)(As + kk * 132 + 64 + ty * 4);              \
        float4 b0 = *(const float4*)(Bs + kk * 132 + tx * 4);                   \
        float4 b1 = *(const float4*)(Bs + kk * 132 + 64 + tx * 4);              \
        float av[8] = {a0.x, a0.y, a0.z, a0.w, a1.x, a1.y, a1.z, a1.w};         \
        float bv[8] = {b0.x, b0.y, b0.z, b0.w, b1.x, b1.y, b1.z, b1.w};         \
        _Pragma("unroll")                                                       \
        for (int i = 0; i < 8; i++)                                             \
            _Pragma("unroll")                                                   \
            for (int j = 0; j < 8; j++) acc[i][j] += av[i] * bv[j];             \
    }

// ---------------- k2: QKV GEMM + scatter -------------------------------------
__global__ void __launch_bounds__(256, 2)
k2_qkv(const float* __restrict__ W, const float* __restrict__ bias) {
    __shared__ float As[16 * 132];
    __shared__ float Bs[16 * 132];
    int tid = threadIdx.x;
    int tx = tid & 15, ty = tid >> 4;
    int row0 = blockIdx.x * 128, col0 = blockIdx.y * 128;
    float acc[8][8] = {};
    for (int k0 = 0; k0 < DIMM; k0 += 16) {
        GEMM_TILE_LOAD(g_xp, W);
        __syncthreads();
        GEMM_MAIN(acc);
        __syncthreads();
    }
    #pragma unroll
    for (int i = 0; i < 8; i++) {
        int r = row0 + ((i < 4) ? ty * 4 + i : 64 + ty * 4 + i - 4);
        #pragma unroll
        for (int j = 0; j < 8; j++) {
            int c = col0 + ((j < 4) ? tx * 4 + j : 64 + tx * 4 + j - 4);
            float v = acc[i][j] + bias[c];
            int h = c / 96, t = c % 96;
            int e = t / 3, s = t - e * 3;
            float* dst = (s == 0) ? g_q : (s == 1) ? g_k : g_v;
            dst[(h * NM + r) * EE + e] = v;
        }
    }
}

// ---------------- k6: output projection GEMM --------------------------------
__global__ void __launch_bounds__(256, 2)
k6_proj(const float* __restrict__ W, const float* __restrict__ bias,
        float* __restrict__ out) {
    __shared__ float As[16 * 132];
    __shared__ float Bs[16 * 132];
    int tid = threadIdx.x;
    int tx = tid & 15, ty = tid >> 4;
    int row0 = blockIdx.x * 128, col0 = blockIdx.y * 128;
    float acc[8][8] = {};
    for (int k0 = 0; k0 < DIMM; k0 += 16) {
        GEMM_TILE_LOAD(g_ao, W);
        __syncthreads();
        GEMM_MAIN(acc);
        __syncthreads();
    }
    #pragma unroll
    for (int i = 0; i < 8; i++) {
        int r = row0 + ((i < 4) ? ty * 4 + i : 64 + ty * 4 + i - 4);
        #pragma unroll
        for (int half = 0; half < 2; half++) {
            int c = col0 + half * 64 + tx * 4;
            float4 v;
            v.x = acc[i][half * 4 + 0] + bias[c + 0];
            v.y = acc[i][half * 4 + 1] + bias[c + 1];
            v.z = acc[i][half * 4 + 2] + bias[c + 2];
            v.w = acc[i][half * 4 + 3] + bias[c + 3];
            *(float4*)(out + r * DIMM + c) = v;
        }
    }
}

// ---------------- k3: per-ball key means -------------------------------------
__global__ void k3_kmean() {
    int t = blockIdx.x * blockDim.x + threadIdx.x;
    int e = t & 31;
    int ball = (t >> 5) & (NB - 1);
    int h = t >> 14;
    const float* base = g_k + (h * NM + ball * MB) * EE + e;
    float s = 0.f;
    #pragma unroll
    for (int m = 0; m < MB; m++) s += base[m * EE];
    g_kmean[t] = s * (1.f / MB);
}

// ---------------- k4: top-2 ball selection (smem tiled, 2 threads/token) ----
__global__ void __launch_bounds__(256)
k4_top2() {
    __shared__ float km[128 * EE];   // 16KB: 128 balls x 32
    int h = blockIdx.y;
    int tok0 = blockIdx.x * 128;
    int tid = threadIdx.x;
    int tl = tid >> 1;               // token within block
    int half = tid & 1;              // ball-range split
    int tok = tok0 + tl;

    float4 q[8];
    const float4* qr = (const float4*)(g_q + (h * NM + tok) * EE);
    #pragma unroll
    for (int i = 0; i < 8; i++) q[i] = qr[i];

    float v1 = -1e30f, v2 = -1e30f;
    int i1 = 0, i2 = 0;

    for (int t = 0; t < 4; t++) {
        int base = t * 128;
        __syncthreads();
        const float4* src = (const float4*)(g_kmean + (h * NB + base) * EE);
        float4* dst = (float4*)km;
        #pragma unroll
        for (int i = 0; i < 4; i++) dst[tid + 256 * i] = src[tid + 256 * i];
        __syncthreads();

        const float* kmh = km + half * 64 * EE;
        #pragma unroll 2
        for (int j = 0; j < 64; j++) {
            const float4* kr = (const float4*)(kmh + j * EE);
            float s0 = 0.f, s1 = 0.f, s2 = 0.f, s3 = 0.f;
            #pragma unroll
            for (int i = 0; i < 8; i++) {
                float4 kv = kr[i];
                s0 += q[i].x * kv.x;
                s1 += q[i].y * kv.y;
                s2 += q[i].z * kv.z;
                s3 += q[i].w * kv.w;
            }
            float s = (s0 + s1) + (s2 + s3);
            int b = base + half * 64 + j;
            if (s > v1) { v2 = v1; i2 = i1; v1 = s; i1 = b; }
            else if (s > v2) { v2 = s; i2 = b; }
        }
    }

    // merge the two half-results across the thread pair
    float pv1 = __shfl_xor_sync(0xffffffffu, v1, 1);
    float pv2 = __shfl_xor_sync(0xffffffffu, v2, 1);
    int   pi1 = __shfl_xor_sync(0xffffffffu, i1, 1);
    int   pi2 = __shfl_xor_sync(0xffffffffu, i2, 1);
    float nv1, nv2; int ni1, ni2;
    if (pv1 > v1) {
        nv1 = pv1; ni1 = pi1;
        if (v1 > pv2) { nv2 = v1; ni2 = i1; } else { nv2 = pv2; ni2 = pi2; }
    } else {
        nv1 = v1; ni1 = i1;
        if (pv1 > v2) { nv2 = pv1; ni2 = pi1; } else { nv2 = v2; ni2 = i2; }
    }
    if (half == 0) {
        g_idx[(h * NM + tok) * 2 + 0] = ni1;
        g_idx[(h * NM + tok) * 2 + 1] = ni2;
    }
}

// ---------------- k5: gathered 32-key attention ------------------------------
__global__ void k5_attn() {
    int warp = (blockIdx.x * blockDim.x + threadIdx.x) >> 5;
    int lane = threadIdx.x & 31;
    int h = warp >> 13;
    int tok = warp & (NM - 1);
    int b0 = g_idx[warp * 2 + 0];
    int b1 = g_idx[warp * 2 + 1];

    int ball = (lane < 16) ? b0 : b1;
    int ktok = ball * MB + (lane & 15);
    const float* krow = g_k + (h * NM + ktok) * EE;
    const float* qrow = g_q + (h * NM + tok) * EE;
    float logit = 0.f;
    #pragma unroll
    for (int e = 0; e < EE; e++) logit += qrow[e] * krow[e];
    logit *= 0.17677669529663688f;

    float m = logit;
    #pragma unroll
    for (int off = 16; off > 0; off >>= 1)
        m = fmaxf(m, __shfl_xor_sync(0xffffffffu, m, off));
    float p = __expf(logit - m);
    float s = p;
    #pragma unroll
    for (int off = 16; off > 0; off >>= 1)
        s += __shfl_xor_sync(0xffffffffu, s, off);
    float attn = p / s;

    float out = 0.f;
    #pragma unroll
    for (int kk = 0; kk < NKEY; kk++) {
        float a = __shfl_sync(0xffffffffu, attn, kk);
        int kt = ((kk < 16) ? b0 : b1) * MB + (kk & 15);
        out += a * g_v[(h * NM + kt) * EE + lane];
    }
    g_ao[tok * DIMM + h * EE + lane] = out;
}

// ---------------- launch ------------------------------------------------------
extern "C" void kernel_launch(void* const* d_in, const int* in_sizes, int n_in,
                              void* d_out, int out_size) {
    const float* x     = (const float*)d_in[0];
    const float* pos   = (const float*)d_in[1];
    const float* Wqkv  = (const float*)d_in[2];
    const float* bqkv  = (const float*)d_in[3];
    const float* Wpe   = (const float*)d_in[4];
    const float* bpe   = (const float*)d_in[5];
    const float* Wproj = (const float*)d_in[6];
    const float* bproj = (const float*)d_in[7];
    float* out = (float*)d_out;

    k1_pe<<<NB, 256>>>(x, pos, Wpe, bpe);
    k2_qkv<<<dim3(NM / 128, 768 / 128), 256>>>(Wqkv, bqkv);
    k3_kmean<<<(NH * NB * EE) / 256, 256>>>();
    k4_top2<<<dim3(NM / 128, NH), 256>>>();
    k5_attn<<<(NH * NM * 32) / 256, 256>>>();
    k6_proj<<<dim3(NM / 128, DIMM / 128), 256>>>(Wproj, bproj, out);
}

// round 3
// speedup vs baseline: 4.1209x; 1.8387x over previous
#include <cuda_runtime.h>

#define NM   8192
#define DIMM 256
#define NH   8
#define EE   32
#define MB   16
#define NB   512
#define NKEY 32

// ---------------- scratch ----------------------------------------------------
__device__ float g_xp[NM * DIMM];
__device__ float g_q[NH * NM * EE];
__device__ float g_k[NH * NM * EE];
__device__ float g_v[NH * NM * EE];
__device__ float g_kmean[NH * NB * EE];
__device__ int   g_idx[NH * NM * 2];
__device__ float g_ao[NM * DIMM];

// ---------------- packed f32x2 helpers ---------------------------------------
typedef unsigned long long ull;
__device__ __forceinline__ ull pack2(float x, float y) {
    ull r; asm("mov.b64 %0, {%1, %2};" : "=l"(r) : "f"(x), "f"(y)); return r;
}
__device__ __forceinline__ ull fma2(ull a, ull b, ull c) {
    ull d; asm("fma.rn.f32x2 %0, %1, %2, %3;" : "=l"(d) : "l"(a), "l"(b), "l"(c));
    return d;
}
__device__ __forceinline__ void unpack2(ull v, float& lo, float& hi) {
    asm("mov.b64 {%0, %1}, %2;" : "=f"(lo), "=f"(hi) : "l"(v));
}

// ---------------- k1: relative-position encoding add ------------------------
__global__ void k1_pe(const float* __restrict__ x, const float* __restrict__ pos,
                      const float* __restrict__ Wpe, const float* __restrict__ bpe) {
    int ball = blockIdx.x;
    int tid  = threadIdx.x;
    __shared__ float rel[MB][3];
    if (tid < 3) {
        float s = 0.f;
        for (int m = 0; m < MB; m++) s += pos[(ball * MB + m) * 3 + tid];
        float mean = s * (1.f / MB);
        for (int m = 0; m < MB; m++)
            rel[m][tid] = pos[(ball * MB + m) * 3 + tid] - mean;
    }
    __syncthreads();
    int d = tid;
    float w0 = Wpe[d * 3 + 0], w1 = Wpe[d * 3 + 1], w2 = Wpe[d * 3 + 2];
    float b  = bpe[d];
    #pragma unroll
    for (int m = 0; m < MB; m++) {
        int t = ball * MB + m;
        g_xp[t * DIMM + d] = x[t * DIMM + d]
                           + rel[m][0] * w0 + rel[m][1] * w1 + rel[m][2] * w2 + b;
    }
}

// ---------------- shared 128x128x16 fp32 GEMM-NT body (f32x2 core) ----------
#define GEMM_TILE_LOAD(Aptr, Bptr)                                              \
    {                                                                           \
        int r  = tid & 127;                                                     \
        int k8 = (tid >> 7) * 8;                                                \
        float4 a0 = *(const float4*)(Aptr + (row0 + r) * DIMM + k0 + k8);       \
        float4 a1 = *(const float4*)(Aptr + (row0 + r) * DIMM + k0 + k8 + 4);   \
        float4 b0 = *(const float4*)(Bptr + (col0 + r) * DIMM + k0 + k8);       \
        float4 b1 = *(const float4*)(Bptr + (col0 + r) * DIMM + k0 + k8 + 4);   \
        As[(k8 + 0) * 132 + r] = a0.x; As[(k8 + 1) * 132 + r] = a0.y;           \
        As[(k8 + 2) * 132 + r] = a0.z; As[(k8 + 3) * 132 + r] = a0.w;           \
        As[(k8 + 4) * 132 + r] = a1.x; As[(k8 + 5) * 132 + r] = a1.y;           \
        As[(k8 + 6) * 132 + r] = a1.z; As[(k8 + 7) * 132 + r] = a1.w;           \
        Bs[(k8 + 0) * 132 + r] = b0.x; Bs[(k8 + 1) * 132 + r] = b0.y;           \
        Bs[(k8 + 2) * 132 + r] = b0.z; Bs[(k8 + 3) * 132 + r] = b0.w;           \
        Bs[(k8 + 4) * 132 + r] = b1.x; Bs[(k8 + 5) * 132 + r] = b1.y;           \
        Bs[(k8 + 6) * 132 + r] = b1.z; Bs[(k8 + 7) * 132 + r] = b1.w;           \
    }

// accp: ull[8][4], pairs over the j (column) dimension
#define GEMM_MAIN_F32X2(accp)                                                   \
    _Pragma("unroll")                                                           \
    for (int kk = 0; kk < 16; kk++) {                                           \
        float4 a0 = *(const float4*)(As + kk * 132 + ty * 4);                   \
        float4 a1 = *(const float4*)(As + kk * 132 + 64 + ty * 4);              \
        float4 b0 = *(const float4*)(Bs + kk * 132 + tx * 4);                   \
        float4 b1 = *(const float4*)(Bs + kk * 132 + 64 + tx * 4);              \
        ull bp[4] = {pack2(b0.x, b0.y), pack2(b0.z, b0.w),                      \
                     pack2(b1.x, b1.y), pack2(b1.z, b1.w)};                     \
        float av[8] = {a0.x, a0.y, a0.z, a0.w, a1.x, a1.y, a1.z, a1.w};         \
        _Pragma("unroll")                                                       \
        for (int i = 0; i < 8; i++) {                                           \
            ull ap = pack2(av[i], av[i]);                                       \
            _Pragma("unroll")                                                   \
            for (int j = 0; j < 4; j++) accp[i][j] = fma2(ap, bp[j], accp[i][j]); \
        }                                                                       \
    }

#define GEMM_UNPACK(accp, acc)                                                  \
    _Pragma("unroll")                                                           \
    for (int i = 0; i < 8; i++)                                                 \
        _Pragma("unroll")                                                       \
        for (int j = 0; j < 4; j++)                                             \
            unpack2(accp[i][j], acc[i][2 * j], acc[i][2 * j + 1]);

// ---------------- k2: QKV GEMM + scatter -------------------------------------
__global__ void __launch_bounds__(256, 2)
k2_qkv(const float* __restrict__ W, const float* __restrict__ bias) {
    __shared__ float As[16 * 132];
    __shared__ float Bs[16 * 132];
    int tid = threadIdx.x;
    int tx = tid & 15, ty = tid >> 4;
    int row0 = blockIdx.x * 128, col0 = blockIdx.y * 128;
    ull accp[8][4] = {};
    for (int k0 = 0; k0 < DIMM; k0 += 16) {
        GEMM_TILE_LOAD(g_xp, W);
        __syncthreads();
        GEMM_MAIN_F32X2(accp);
        __syncthreads();
    }
    float acc[8][8];
    GEMM_UNPACK(accp, acc);
    #pragma unroll
    for (int i = 0; i < 8; i++) {
        int r = row0 + ((i < 4) ? ty * 4 + i : 64 + ty * 4 + i - 4);
        #pragma unroll
        for (int j = 0; j < 8; j++) {
            int c = col0 + ((j < 4) ? tx * 4 + j : 64 + tx * 4 + j - 4);
            float v = acc[i][j] + bias[c];
            int h = c / 96, t = c % 96;
            int e = t / 3, s = t - e * 3;
            float* dst = (s == 0) ? g_q : (s == 1) ? g_k : g_v;
            dst[(h * NM + r) * EE + e] = v;
        }
    }
}

// ---------------- k6: output projection GEMM --------------------------------
__global__ void __launch_bounds__(256, 2)
k6_proj(const float* __restrict__ W, const float* __restrict__ bias,
        float* __restrict__ out) {
    __shared__ float As[16 * 132];
    __shared__ float Bs[16 * 132];
    int tid = threadIdx.x;
    int tx = tid & 15, ty = tid >> 4;
    int row0 = blockIdx.x * 128, col0 = blockIdx.y * 128;
    ull accp[8][4] = {};
    for (int k0 = 0; k0 < DIMM; k0 += 16) {
        GEMM_TILE_LOAD(g_ao, W);
        __syncthreads();
        GEMM_MAIN_F32X2(accp);
        __syncthreads();
    }
    float acc[8][8];
    GEMM_UNPACK(accp, acc);
    #pragma unroll
    for (int i = 0; i < 8; i++) {
        int r = row0 + ((i < 4) ? ty * 4 + i : 64 + ty * 4 + i - 4);
        #pragma unroll
        for (int half = 0; half < 2; half++) {
            int c = col0 + half * 64 + tx * 4;
            float4 v;
            v.x = acc[i][half * 4 + 0] + bias[c + 0];
            v.y = acc[i][half * 4 + 1] + bias[c + 1];
            v.z = acc[i][half * 4 + 2] + bias[c + 2];
            v.w = acc[i][half * 4 + 3] + bias[c + 3];
            *(float4*)(out + r * DIMM + c) = v;
        }
    }
}

// ---------------- k3: per-ball key means -------------------------------------
__global__ void k3_kmean() {
    int t = blockIdx.x * blockDim.x + threadIdx.x;
    int e = t & 31;
    int ball = (t >> 5) & (NB - 1);
    int h = t >> 14;
    const float* base = g_k + (h * NM + ball * MB) * EE + e;
    float s = 0.f;
    #pragma unroll
    for (int m = 0; m < MB; m++) s += base[m * EE];
    g_kmean[t] = s * (1.f / MB);
}

// ---------------- k4: sim GEMM (128 tok x 128 ball tiles) + in-reg top-2 ----
// block: 128 tokens of head h; 4 ball-tiles of 128; thread = 8 tok x 8 ball.
__global__ void __launch_bounds__(256)
k4_top2() {
    __shared__ float As[32 * 132];   // [kk][token]
    __shared__ float Bs[32 * 132];   // [kk][ball]
    int h = blockIdx.y;
    int tok0 = blockIdx.x * 128;
    int tid = threadIdx.x;
    int tx = tid & 15, ty = tid >> 4;

    // stage q block, k-major (once)
    #pragma unroll
    for (int l = 0; l < 4; l++) {
        int i = tid + l * 256;           // 0..1023 float4s
        int t = i >> 3;                  // token 0..127
        int e4 = i & 7;                  // float4 within 32-dim row
        float4 v = *(const float4*)(g_q + (h * NM + tok0 + t) * EE + e4 * 4);
        As[(e4 * 4 + 0) * 132 + t] = v.x;
        As[(e4 * 4 + 1) * 132 + t] = v.y;
        As[(e4 * 4 + 2) * 132 + t] = v.z;
        As[(e4 * 4 + 3) * 132 + t] = v.w;
    }

    float v1[8], v2[8];
    int   i1[8], i2[8];
    #pragma unroll
    for (int i = 0; i < 8; i++) { v1[i] = -1e30f; v2[i] = -1e30f; i1[i] = 0; i2[i] = 0; }

    for (int tile = 0; tile < 4; tile++) {
        int ball0 = tile * 128;
        __syncthreads();
        // stage kmean tile, k-major
        #pragma unroll
        for (int l = 0; l < 4; l++) {
            int i = tid + l * 256;
            int b = i >> 3;
            int e4 = i & 7;
            float4 v = *(const float4*)(g_kmean + (h * NB + ball0 + b) * EE + e4 * 4);
            Bs[(e4 * 4 + 0) * 132 + b] = v.x;
            Bs[(e4 * 4 + 1) * 132 + b] = v.y;
            Bs[(e4 * 4 + 2) * 132 + b] = v.z;
            Bs[(e4 * 4 + 3) * 132 + b] = v.w;
        }
        __syncthreads();

        ull accp[8][4] = {};
        #pragma unroll
        for (int kk = 0; kk < 32; kk++) {
            float4 a0 = *(const float4*)(As + kk * 132 + ty * 4);
            float4 a1 = *(const float4*)(As + kk * 132 + 64 + ty * 4);
            float4 b0 = *(const float4*)(Bs + kk * 132 + tx * 4);
            float4 b1 = *(const float4*)(Bs + kk * 132 + 64 + tx * 4);
            ull bp[4] = {pack2(b0.x, b0.y), pack2(b0.z, b0.w),
                         pack2(b1.x, b1.y), pack2(b1.z, b1.w)};
            float av[8] = {a0.x, a0.y, a0.z, a0.w, a1.x, a1.y, a1.z, a1.w};
            #pragma unroll
            for (int i = 0; i < 8; i++) {
                ull ap = pack2(av[i], av[i]);
                #pragma unroll
                for (int j = 0; j < 4; j++) accp[i][j] = fma2(ap, bp[j], accp[i][j]);
            }
        }

        // fold this tile's 8 ball-scores per token into running top-2
        #pragma unroll
        for (int i = 0; i < 8; i++) {
            #pragma unroll
            for (int j = 0; j < 4; j++) {
                float slo, shi;
                unpack2(accp[i][j], slo, shi);
                int cbase = (j < 2) ? tx * 4 + j * 2 : 64 + tx * 4 + (j - 2) * 2;
                int blo = ball0 + cbase;
                int bhi = blo + 1;
                if (slo > v1[i]) { v2[i] = v1[i]; i2[i] = i1[i]; v1[i] = slo; i1[i] = blo; }
                else if (slo > v2[i]) { v2[i] = slo; i2[i] = blo; }
                if (shi > v1[i]) { v2[i] = v1[i]; i2[i] = i1[i]; v1[i] = shi; i1[i] = bhi; }
                else if (shi > v2[i]) { v2[i] = shi; i2[i] = bhi; }
            }
        }
    }

    // merge across the 16 lanes (tx) sharing each token group
    #pragma unroll
    for (int i = 0; i < 8; i++) {
        float a1v = v1[i], a2v = v2[i];
        int   a1i = i1[i], a2i = i2[i];
        #pragma unroll
        for (int m = 1; m < 16; m <<= 1) {
            float o1v = __shfl_xor_sync(0xffffffffu, a1v, m);
            float o2v = __shfl_xor_sync(0xffffffffu, a2v, m);
            int   o1i = __shfl_xor_sync(0xffffffffu, a1i, m);
            int   o2i = __shfl_xor_sync(0xffffffffu, a2i, m);
            if (o1v > a1v) {
                if (a1v > o2v) { a2v = a1v; a2i = a1i; }
                else           { a2v = o2v; a2i = o2i; }
                a1v = o1v; a1i = o1i;
            } else {
                if (o1v > a2v) { a2v = o1v; a2i = o1i; }
            }
        }
        if (tx == 0) {
            int tok = tok0 + ((i < 4) ? ty * 4 + i : 64 + ty * 4 + i - 4);
            g_idx[(h * NM + tok) * 2 + 0] = a1i;
            g_idx[(h * NM + tok) * 2 + 1] = a2i;
        }
    }
}

// ---------------- k5: gathered 32-key attention ------------------------------
__global__ void k5_attn() {
    int warp = (blockIdx.x * blockDim.x + threadIdx.x) >> 5;
    int lane = threadIdx.x & 31;
    int h = warp >> 13;
    int tok = warp & (NM - 1);
    int b0 = g_idx[warp * 2 + 0];
    int b1 = g_idx[warp * 2 + 1];

    int ball = (lane < 16) ? b0 : b1;
    int ktok = ball * MB + (lane & 15);
    const float4* krow = (const float4*)(g_k + (h * NM + ktok) * EE);
    const float4* qrow = (const float4*)(g_q + (h * NM + tok) * EE);
    float logit = 0.f;
    #pragma unroll
    for (int e = 0; e < 8; e++) {
        float4 qv = qrow[e], kv = krow[e];
        logit += qv.x * kv.x + qv.y * kv.y + qv.z * kv.z + qv.w * kv.w;
    }
    logit *= 0.17677669529663688f;

    float m = logit;
    #pragma unroll
    for (int off = 16; off > 0; off >>= 1)
        m = fmaxf(m, __shfl_xor_sync(0xffffffffu, m, off));
    float p = __expf(logit - m);
    float s = p;
    #pragma unroll
    for (int off = 16; off > 0; off >>= 1)
        s += __shfl_xor_sync(0xffffffffu, s, off);
    float attn = p / s;

    float out = 0.f;
    #pragma unroll
    for (int kk = 0; kk < NKEY; kk++) {
        float a = __shfl_sync(0xffffffffu, attn, kk);
        int kt = ((kk < 16) ? b0 : b1) * MB + (kk & 15);
        out += a * g_v[(h * NM + kt) * EE + lane];
    }
    g_ao[tok * DIMM + h * EE + lane] = out;
}

// ---------------- launch ------------------------------------------------------
extern "C" void kernel_launch(void* const* d_in, const int* in_sizes, int n_in,
                              void* d_out, int out_size) {
    const float* x     = (const float*)d_in[0];
    const float* pos   = (const float*)d_in[1];
    const float* Wqkv  = (const float*)d_in[2];
    const float* bqkv  = (const float*)d_in[3];
    const float* Wpe   = (const float*)d_in[4];
    const float* bpe   = (const float*)d_in[5];
    const float* Wproj = (const float*)d_in[6];
    const float* bproj = (const float*)d_in[7];
    float* out = (float*)d_out;

    k1_pe<<<NB, 256>>>(x, pos, Wpe, bpe);
    k2_qkv<<<dim3(NM / 128, 768 / 128), 256>>>(Wqkv, bqkv);
    k3_kmean<<<(NH * NB * EE) / 256, 256>>>();
    k4_top2<<<dim3(NM / 128, NH), 256>>>();
    k5_attn<<<(NH * NM * 32) / 256, 256>>>();
    k6_proj<<<dim3(NM / 128, DIMM / 128), 256>>>(Wproj, bproj, out);
}

// round 6
// speedup vs baseline: 4.2104x; 1.0217x over previous
#include <cuda_runtime.h>
#include <cuda_bf16.h>
#include <cstdint>

#define NM   8192
#define DIMM 256
#define NH   8
#define EE   32
#define MB   16
#define NB   512
#define NKEY 32
#define NQKV 768

// ---------------- scratch ----------------------------------------------------
__device__ float g_xp[NM * DIMM];                         // fp32 PE'd x
__device__ __align__(16) __nv_bfloat16 g_xph[NM * DIMM];  // bf16 splits of xp
__device__ __align__(16) __nv_bfloat16 g_xpl[NM * DIMM];
__device__ float g_wqk[512 * DIMM];                       // permuted fp32 Q,K weights
__device__ __align__(16) __nv_bfloat16 g_wvh[256 * DIMM]; // permuted V weight splits
__device__ __align__(16) __nv_bfloat16 g_wvl[256 * DIMM];
__device__ __align__(16) __nv_bfloat16 g_wph[DIMM * DIMM];
__device__ __align__(16) __nv_bfloat16 g_wpl[DIMM * DIMM];
__device__ __align__(16) __nv_bfloat16 g_aoh[NM * DIMM];
__device__ __align__(16) __nv_bfloat16 g_aol[NM * DIMM];
__device__ float g_q[NH * NM * EE];
__device__ float g_k[NH * NM * EE];
__device__ float g_v[NH * NM * EE];
__device__ float g_kmean[NH * NB * EE];
__device__ int   g_idx[NH * NM * 2];

// ---------------- packed f32x2 helpers ----------------------------------------
typedef unsigned long long ull;
__device__ __forceinline__ ull pack2(float x, float y) {
    ull r; asm("mov.b64 %0, {%1, %2};" : "=l"(r) : "f"(x), "f"(y)); return r;
}
__device__ __forceinline__ ull fma2(ull a, ull b, ull c) {
    ull d; asm("fma.rn.f32x2 %0, %1, %2, %3;" : "=l"(d) : "l"(a), "l"(b), "l"(c));
    return d;
}
__device__ __forceinline__ void unpack2(ull v, float& lo, float& hi) {
    asm("mov.b64 {%0, %1}, %2;" : "=f"(lo), "=f"(hi) : "l"(v));
}

// ---------------- mma.sync helpers ---------------------------------------------
__device__ __forceinline__ uint32_t smem_u32(const void* p) {
    uint32_t a;
    asm("{ .reg .u64 t; cvta.to.shared.u64 t, %1; cvt.u32.u64 %0, t; }" : "=r"(a) : "l"(p));
    return a;
}
__device__ __forceinline__ uint32_t swz_addr(uint32_t base, int r, int cb) {
    uint32_t off = (uint32_t)(r * 128 + cb);
    off ^= (off >> 3) & 0x70;
    return base + off;
}
__device__ __forceinline__ void ldsm4(uint32_t& r0, uint32_t& r1, uint32_t& r2,
                                      uint32_t& r3, uint32_t addr) {
    asm volatile("ldmatrix.sync.aligned.m8n8.x4.shared.b16 {%0,%1,%2,%3}, [%4];"
                 : "=r"(r0), "=r"(r1), "=r"(r2), "=r"(r3) : "r"(addr));
}
__device__ __forceinline__ void mma16816(float* d, const uint32_t* a,
                                         uint32_t b0, uint32_t b1) {
    asm volatile(
        "mma.sync.aligned.m16n8k16.row.col.f32.bf16.bf16.f32 "
        "{%0,%1,%2,%3}, {%4,%5,%6,%7}, {%8,%9}, {%0,%1,%2,%3};"
        : "+f"(d[0]), "+f"(d[1]), "+f"(d[2]), "+f"(d[3])
        : "r"(a[0]), "r"(a[1]), "r"(a[2]), "r"(a[3]), "r"(b0), "r"(b1));
}

// ---------------- k0: weight permutation + splits --------------------------------
// QKV weight rows: c = h*96 + e*3 + s (s: 0=q 1=k 2=v).
// Q,K rows -> fp32 g_wqk at row h*64 + e*2 + s.
// V rows   -> bf16 splits g_wvh/l at row h*32 + e.
__global__ void kconv_w(const float* __restrict__ Wq, const float* __restrict__ Wp) {
    int i = blockIdx.x * 256 + threadIdx.x;    // 1024 blocks
    if (i < NQKV * DIMM) {
        int c = i >> 8, d = i & 255;
        int h = c / 96, t = c % 96, e = t / 3, s = t - e * 3;
        float v = Wq[i];
        if (s < 2) {
            g_wqk[(h * 64 + e * 2 + s) * DIMM + d] = v;
        } else {
            __nv_bfloat16 hh = __float2bfloat16(v);
            int idx = (h * 32 + e) * DIMM + d;
            g_wvh[idx] = hh;
            g_wvl[idx] = __float2bfloat16(v - __bfloat162float(hh));
        }
    } else {
        int j = i - NQKV * DIMM;
        float v = Wp[j];
        __nv_bfloat16 hh = __float2bfloat16(v);
        g_wph[j] = hh;
        g_wpl[j] = __float2bfloat16(v - __bfloat162float(hh));
    }
}

// ---------------- k1: PE add; write fp32 + bf16 splits ----------------------------
__global__ void k1_pe(const float* __restrict__ x, const float* __restrict__ pos,
                      const float* __restrict__ Wpe, const float* __restrict__ bpe) {
    int ball = blockIdx.x;
    int tid  = threadIdx.x;
    __shared__ float rel[MB][3];
    if (tid < 3) {
        float s = 0.f;
        for (int m = 0; m < MB; m++) s += pos[(ball * MB + m) * 3 + tid];
        float mean = s * (1.f / MB);
        for (int m = 0; m < MB; m++)
            rel[m][tid] = pos[(ball * MB + m) * 3 + tid] - mean;
    }
    __syncthreads();
    int d = tid;
    float w0 = Wpe[d * 3 + 0], w1 = Wpe[d * 3 + 1], w2 = Wpe[d * 3 + 2];
    float b  = bpe[d];
    #pragma unroll
    for (int m = 0; m < MB; m++) {
        int t = ball * MB + m;
        float v = x[t * DIMM + d]
                + rel[m][0] * w0 + rel[m][1] * w1 + rel[m][2] * w2 + b;
        g_xp[t * DIMM + d] = v;
        __nv_bfloat16 h = __float2bfloat16(v);
        g_xph[t * DIMM + d] = h;
        g_xpl[t * DIMM + d] = __float2bfloat16(v - __bfloat162float(h));
    }
}

// ---------------- fp32 f32x2 GEMM-NT for Q,K (N=512) ------------------------------
#define GEMM_TILE_LOAD(Aptr, Bptr)                                              \
    {                                                                           \
        int r  = tid & 127;                                                     \
        int k8 = (tid >> 7) * 8;                                                \
        float4 a0 = *(const float4*)(Aptr + (row0 + r) * DIMM + k0 + k8);       \
        float4 a1 = *(const float4*)(Aptr + (row0 + r) * DIMM + k0 + k8 + 4);   \
        float4 b0 = *(const float4*)(Bptr + (col0 + r) * DIMM + k0 + k8);       \
        float4 b1 = *(const float4*)(Bptr + (col0 + r) * DIMM + k0 + k8 + 4);   \
        As[(k8 + 0) * 132 + r] = a0.x; As[(k8 + 1) * 132 + r] = a0.y;           \
        As[(k8 + 2) * 132 + r] = a0.z; As[(k8 + 3) * 132 + r] = a0.w;           \
        As[(k8 + 4) * 132 + r] = a1.x; As[(k8 + 5) * 132 + r] = a1.y;           \
        As[(k8 + 6) * 132 + r] = a1.z; As[(k8 + 7) * 132 + r] = a1.w;           \
        Bs[(k8 + 0) * 132 + r] = b0.x; Bs[(k8 + 1) * 132 + r] = b0.y;           \
        Bs[(k8 + 2) * 132 + r] = b0.z; Bs[(k8 + 3) * 132 + r] = b0.w;           \
        Bs[(k8 + 4) * 132 + r] = b1.x; Bs[(k8 + 5) * 132 + r] = b1.y;           \
        Bs[(k8 + 6) * 132 + r] = b1.z; Bs[(k8 + 7) * 132 + r] = b1.w;           \
    }

__global__ void __launch_bounds__(256, 2)
k2_qk(const float* __restrict__ bias) {
    __shared__ float As[16 * 132];
    __shared__ float Bs[16 * 132];
    int tid = threadIdx.x;
    int tx = tid & 15, ty = tid >> 4;
    int row0 = blockIdx.x * 128, col0 = blockIdx.y * 128;
    ull accp[8][4] = {};
    for (int k0 = 0; k0 < DIMM; k0 += 16) {
        GEMM_TILE_LOAD(g_xp, g_wqk);
        __syncthreads();
        #pragma unroll
        for (int kk = 0; kk < 16; kk++) {
            float4 a0 = *(const float4*)(As + kk * 132 + ty * 4);
            float4 a1 = *(const float4*)(As + kk * 132 + 64 + ty * 4);
            float4 b0 = *(const float4*)(Bs + kk * 132 + tx * 4);
            float4 b1 = *(const float4*)(Bs + kk * 132 + 64 + tx * 4);
            ull bp[4] = {pack2(b0.x, b0.y), pack2(b0.z, b0.w),
                         pack2(b1.x, b1.y), pack2(b1.z, b1.w)};
            float av[8] = {a0.x, a0.y, a0.z, a0.w, a1.x, a1.y, a1.z, a1.w};
            #pragma unroll
            for (int i = 0; i < 8; i++) {
                ull ap = pack2(av[i], av[i]);
                #pragma unroll
                for (int j = 0; j < 4; j++) accp[i][j] = fma2(ap, bp[j], accp[i][j]);
            }
        }
        __syncthreads();
    }
    float acc[8][8];
    #pragma unroll
    for (int i = 0; i < 8; i++)
        #pragma unroll
        for (int j = 0; j < 4; j++)
            unpack2(accp[i][j], acc[i][2 * j], acc[i][2 * j + 1]);
    #pragma unroll
    for (int i = 0; i < 8; i++) {
        int r = row0 + ((i < 4) ? ty * 4 + i : 64 + ty * 4 + i - 4);
        #pragma unroll
        for (int j = 0; j < 8; j++) {
            int cp = col0 + ((j < 4) ? tx * 4 + j : 64 + tx * 4 + j - 4);
            int h = cp >> 6, r6 = cp & 63;
            int e = r6 >> 1, s = r6 & 1;
            float v = acc[i][j] + bias[h * 96 + e * 3 + s];
            float* dst = (s == 0) ? g_q : g_k;
            dst[(h * NM + r) * EE + e] = v;
        }
    }
}

// ---------------- split-bf16 HMMA GEMM-NT (V and proj) -----------------------------
// MODE 0: A=g_xph/l, B=g_wvh/l (N=256) -> g_v (+ V bias).
// MODE 1: A=g_aoh/l, B=g_wph/l (N=256) -> out (+ proj bias).
template<int MODE>
__global__ void __launch_bounds__(256, 2)
gemm_mma(const float* __restrict__ bias, float* __restrict__ out) {
    extern __shared__ char dsm_raw[];
    int tid = threadIdx.x;
    int wid = tid >> 5, lane = tid & 31;
    int row0 = blockIdx.x * 128, col0 = blockIdx.y * 128;
    int warp_m = (wid & 1) * 64;
    int warp_n = (wid >> 1) * 32;

    const __nv_bfloat16* Ah = (MODE == 0) ? g_xph : g_aoh;
    const __nv_bfloat16* Al = (MODE == 0) ? g_xpl : g_aol;
    const __nv_bfloat16* Bh = (MODE == 0) ? g_wvh : g_wph;
    const __nv_bfloat16* Bl = (MODE == 0) ? g_wvl : g_wpl;

    uint32_t raw = smem_u32(dsm_raw);
    uint32_t sbase = (raw + 1023u) & ~1023u;
    char* dsm = dsm_raw + (sbase - raw);

    float acc[4][4][4] = {};
    int lr = lane & 7;
    int g  = lane >> 3;

    for (int chunk = 0; chunk < 4; chunk++) {
        int k0 = chunk * 64;
        __syncthreads();
        #pragma unroll
        for (int b = 0; b < 4; b++) {
            const __nv_bfloat16* src = (b == 0) ? Ah : (b == 1) ? Al : (b == 2) ? Bh : Bl;
            int rbase = (b < 2) ? row0 : col0;
            #pragma unroll
            for (int l = 0; l < 4; l++) {
                int u = tid + l * 256;
                int r = u >> 3, c = u & 7;
                uint4 val = *(const uint4*)(src + (rbase + r) * DIMM + k0 + c * 8);
                uint32_t off = (uint32_t)(r * 128 + c * 16);
                off ^= (off >> 3) & 0x70;
                *(uint4*)(dsm + b * 16384 + off) = val;
            }
        }
        __syncthreads();

        uint32_t aBuf[2] = {sbase, sbase + 16384};
        uint32_t bBuf[2] = {sbase + 32768, sbase + 49152};

        #pragma unroll
        for (int pass = 0; pass < 3; pass++) {
            uint32_t abase = aBuf[(pass == 2) ? 1 : 0];
            uint32_t bbase = bBuf[(pass == 1) ? 1 : 0];
            #pragma unroll
            for (int ks = 0; ks < 4; ks++) {
                uint32_t af[4][4];
                #pragma unroll
                for (int mi = 0; mi < 4; mi++) {
                    int row = warp_m + mi * 16 + ((g & 1) << 3) + lr;
                    int cb  = ks * 32 + ((g >> 1) << 4);
                    ldsm4(af[mi][0], af[mi][1], af[mi][2], af[mi][3],
                          swz_addr(abase, row, cb));
                }
                uint32_t bf[4][2];
                #pragma unroll
                for (int p = 0; p < 2; p++) {
                    int n  = warp_n + p * 16 + ((g >> 1) << 3) + lr;
                    int cb = ks * 32 + ((g & 1) << 4);
                    uint32_t r0, r1, r2, r3;
                    ldsm4(r0, r1, r2, r3, swz_addr(bbase, n, cb));
                    bf[p * 2 + 0][0] = r0; bf[p * 2 + 0][1] = r1;
                    bf[p * 2 + 1][0] = r2; bf[p * 2 + 1][1] = r3;
                }
                #pragma unroll
                for (int mi = 0; mi < 4; mi++)
                    #pragma unroll
                    for (int nj = 0; nj < 4; nj++)
                        mma16816(acc[mi][nj], af[mi], bf[nj][0], bf[nj][1]);
            }
        }
    }

    int erow = lane >> 2;
    int ecol = (lane & 3) * 2;
    #pragma unroll
    for (int mi = 0; mi < 4; mi++) {
        #pragma unroll
        for (int nj = 0; nj < 4; nj++) {
            #pragma unroll
            for (int half = 0; half < 2; half++) {
                int r = row0 + warp_m + mi * 16 + erow + half * 8;
                #pragma unroll
                for (int rg = 0; rg < 2; rg++) {
                    int cp = col0 + warp_n + nj * 8 + ecol + rg;
                    if (MODE == 0) {
                        int h = cp >> 5, e = cp & 31;
                        float v = acc[mi][nj][half * 2 + rg] + bias[h * 96 + e * 3 + 2];
                        g_v[(h * NM + r) * EE + e] = v;
                    } else {
                        float v = acc[mi][nj][half * 2 + rg] + bias[cp];
                        out[r * DIMM + cp] = v;
                    }
                }
            }
        }
    }
}

// ---------------- k3: per-ball key means --------------------------------------------
__global__ void k3_kmean() {
    int t = blockIdx.x * blockDim.x + threadIdx.x;
    int e = t & 31;
    int ball = (t >> 5) & (NB - 1);
    int h = t >> 14;
    const float* base = g_k + (h * NM + ball * MB) * EE + e;
    float s = 0.f;
    #pragma unroll
    for (int m = 0; m < MB; m++) s += base[m * EE];
    g_kmean[t] = s * (1.f / MB);
}

// ---------------- k4: sim GEMM + in-register top-2 ----------------------------------
__global__ void __launch_bounds__(256)
k4_top2() {
    __shared__ float As[32 * 132];
    __shared__ float Bs[32 * 132];
    int h = blockIdx.y;
    int tok0 = blockIdx.x * 128;
    int tid = threadIdx.x;
    int tx = tid & 15, ty = tid >> 4;

    #pragma unroll
    for (int l = 0; l < 4; l++) {
        int i = tid + l * 256;
        int t = i >> 3;
        int e4 = i & 7;
        float4 v = *(const float4*)(g_q + (h * NM + tok0 + t) * EE + e4 * 4);
        As[(e4 * 4 + 0) * 132 + t] = v.x;
        As[(e4 * 4 + 1) * 132 + t] = v.y;
        As[(e4 * 4 + 2) * 132 + t] = v.z;
        As[(e4 * 4 + 3) * 132 + t] = v.w;
    }

    float v1[8], v2[8];
    int   i1[8], i2[8];
    #pragma unroll
    for (int i = 0; i < 8; i++) { v1[i] = -1e30f; v2[i] = -1e30f; i1[i] = 0; i2[i] = 0; }

    for (int tile = 0; tile < 4; tile++) {
        int ball0 = tile * 128;
        __syncthreads();
        #pragma unroll
        for (int l = 0; l < 4; l++) {
            int i = tid + l * 256;
            int b = i >> 3;
            int e4 = i & 7;
            float4 v = *(const float4*)(g_kmean + (h * NB + ball0 + b) * EE + e4 * 4);
            Bs[(e4 * 4 + 0) * 132 + b] = v.x;
            Bs[(e4 * 4 + 1) * 132 + b] = v.y;
            Bs[(e4 * 4 + 2) * 132 + b] = v.z;
            Bs[(e4 * 4 + 3) * 132 + b] = v.w;
        }
        __syncthreads();

        ull accp[8][4] = {};
        #pragma unroll
        for (int kk = 0; kk < 32; kk++) {
            float4 a0 = *(const float4*)(As + kk * 132 + ty * 4);
            float4 a1 = *(const float4*)(As + kk * 132 + 64 + ty * 4);
            float4 b0 = *(const float4*)(Bs + kk * 132 + tx * 4);
            float4 b1 = *(const float4*)(Bs + kk * 132 + 64 + tx * 4);
            ull bp[4] = {pack2(b0.x, b0.y), pack2(b0.z, b0.w),
                         pack2(b1.x, b1.y), pack2(b1.z, b1.w)};
            float av[8] = {a0.x, a0.y, a0.z, a0.w, a1.x, a1.y, a1.z, a1.w};
            #pragma unroll
            for (int i = 0; i < 8; i++) {
                ull ap = pack2(av[i], av[i]);
                #pragma unroll
                for (int j = 0; j < 4; j++) accp[i][j] = fma2(ap, bp[j], accp[i][j]);
            }
        }

        #pragma unroll
        for (int i = 0; i < 8; i++) {
            #pragma unroll
            for (int j = 0; j < 4; j++) {
                float slo, shi;
                unpack2(accp[i][j], slo, shi);
                int cbase = (j < 2) ? tx * 4 + j * 2 : 64 + tx * 4 + (j - 2) * 2;
                int blo = ball0 + cbase;
                int bhi = blo + 1;
                if (slo > v1[i]) { v2[i] = v1[i]; i2[i] = i1[i]; v1[i] = slo; i1[i] = blo; }
                else if (slo > v2[i]) { v2[i] = slo; i2[i] = blo; }
                if (shi > v1[i]) { v2[i] = v1[i]; i2[i] = i1[i]; v1[i] = shi; i1[i] = bhi; }
                else if (shi > v2[i]) { v2[i] = shi; i2[i] = bhi; }
            }
        }
    }

    #pragma unroll
    for (int i = 0; i < 8; i++) {
        float a1v = v1[i], a2v = v2[i];
        int   a1i = i1[i], a2i = i2[i];
        #pragma unroll
        for (int m = 1; m < 16; m <<= 1) {
            float o1v = __shfl_xor_sync(0xffffffffu, a1v, m);
            float o2v = __shfl_xor_sync(0xffffffffu, a2v, m);
            int   o1i = __shfl_xor_sync(0xffffffffu, a1i, m);
            int   o2i = __shfl_xor_sync(0xffffffffu, a2i, m);
            if (o1v > a1v) {
                if (a1v > o2v) { a2v = a1v; a2i = a1i; }
                else           { a2v = o2v; a2i = o2i; }
                a1v = o1v; a1i = o1i;
            } else {
                if (o1v > a2v) { a2v = o1v; a2i = o1i; }
            }
        }
        if (tx == 0) {
            int tok = tok0 + ((i < 4) ? ty * 4 + i : 64 + ty * 4 + i - 4);
            g_idx[(h * NM + tok) * 2 + 0] = a1i;
            g_idx[(h * NM + tok) * 2 + 1] = a2i;
        }
    }
}

// ---------------- k5: gathered 32-key attention + bf16 split out --------------------
__global__ void k5_attn() {
    int warp = (blockIdx.x * blockDim.x + threadIdx.x) >> 5;
    int lane = threadIdx.x & 31;
    int h = warp >> 13;
    int tok = warp & (NM - 1);
    int b0 = g_idx[warp * 2 + 0];
    int b1 = g_idx[warp * 2 + 1];

    int ball = (lane < 16) ? b0 : b1;
    int ktok = ball * MB + (lane & 15);
    const float4* krow = (const float4*)(g_k + (h * NM + ktok) * EE);
    const float4* qrow = (const float4*)(g_q + (h * NM + tok) * EE);
    float logit = 0.f;
    #pragma unroll
    for (int e = 0; e < 8; e++) {
        float4 qv = qrow[e], kv = krow[e];
        logit += qv.x * kv.x + qv.y * kv.y + qv.z * kv.z + qv.w * kv.w;
    }
    logit *= 0.17677669529663688f;

    float m = logit;
    #pragma unroll
    for (int off = 16; off > 0; off >>= 1)
        m = fmaxf(m, __shfl_xor_sync(0xffffffffu, m, off));
    float p = __expf(logit - m);
    float s = p;
    #pragma unroll
    for (int off = 16; off > 0; off >>= 1)
        s += __shfl_xor_sync(0xffffffffu, s, off);
    float attn = p / s;

    float out = 0.f;
    #pragma unroll
    for (int kk = 0; kk < NKEY; kk++) {
        float a = __shfl_sync(0xffffffffu, attn, kk);
        int kt = ((kk < 16) ? b0 : b1) * MB + (kk & 15);
        out += a * g_v[(h * NM + kt) * EE + lane];
    }
    int oi = tok * DIMM + h * EE + lane;
    __nv_bfloat16 hi = __float2bfloat16(out);
    g_aoh[oi] = hi;
    g_aol[oi] = __float2bfloat16(out - __bfloat162float(hi));
}

// ---------------- launch --------------------------------------------------------------
extern "C" void kernel_launch(void* const* d_in, const int* in_sizes, int n_in,
                              void* d_out, int out_size) {
    const float* x     = (const float*)d_in[0];
    const float* pos   = (const float*)d_in[1];
    const float* Wqkv  = (const float*)d_in[2];
    const float* bqkv  = (const float*)d_in[3];
    const float* Wpe   = (const float*)d_in[4];
    const float* bpe   = (const float*)d_in[5];
    const float* Wproj = (const float*)d_in[6];
    const float* bproj = (const float*)d_in[7];
    float* out = (float*)d_out;

    const int DSMEM = 65536 + 1024;
    cudaFuncSetAttribute(gemm_mma<0>, cudaFuncAttributeMaxDynamicSharedMemorySize, DSMEM);
    cudaFuncSetAttribute(gemm_mma<1>, cudaFuncAttributeMaxDynamicSharedMemorySize, DSMEM);

    kconv_w<<<1024, 256>>>(Wqkv, Wproj);
    k1_pe<<<NB, 256>>>(x, pos, Wpe, bpe);
    k2_qk<<<dim3(NM / 128, 512 / 128), 256>>>(bqkv);
    gemm_mma<0><<<dim3(NM / 128, 256 / 128), 256, DSMEM>>>(bqkv, nullptr);
    k3_kmean<<<(NH * NB * EE) / 256, 256>>>();
    k4_top2<<<dim3(NM / 128, NH), 256>>>();
    k5_attn<<<(NH * NM * 32) / 256, 256>>>();
    gemm_mma<1><<<dim3(NM / 128, DIMM / 128), 256, DSMEM>>>(bproj, out);
}

// round 7
// speedup vs baseline: 4.9285x; 1.1705x over previous
#include <cuda_runtime.h>
#include <cuda_bf16.h>
#include <cstdint>

#define NM   8192
#define DIMM 256
#define NH   8
#define EE   32
#define MB   16
#define NB   512
#define NKEY 32
#define NQKV 768

// ---------------- scratch ----------------------------------------------------
__device__ float g_xp[NM * DIMM];                         // fp32 PE'd x
__device__ __align__(16) __nv_bfloat16 g_xph[NM * DIMM];  // bf16 splits of xp
__device__ __align__(16) __nv_bfloat16 g_xpl[NM * DIMM];
__device__ float g_wqk[512 * DIMM];                       // permuted fp32 Q,K weights
__device__ __align__(16) __nv_bfloat16 g_wvh[256 * DIMM]; // permuted V weight splits
__device__ __align__(16) __nv_bfloat16 g_wvl[256 * DIMM];
__device__ __align__(16) __nv_bfloat16 g_wph[DIMM * DIMM];
__device__ __align__(16) __nv_bfloat16 g_wpl[DIMM * DIMM];
__device__ __align__(16) __nv_bfloat16 g_aoh[NM * DIMM];
__device__ __align__(16) __nv_bfloat16 g_aol[NM * DIMM];
__device__ float g_q[NH * NM * EE];
__device__ float g_k[NH * NM * EE];
__device__ float g_v[NH * NM * EE];
__device__ float g_kmean[NH * NB * EE];
__device__ int   g_idx[NH * NM * 2];

// ---------------- packed f32x2 helpers ----------------------------------------
typedef unsigned long long ull;
__device__ __forceinline__ ull pack2(float x, float y) {
    ull r; asm("mov.b64 %0, {%1, %2};" : "=l"(r) : "f"(x), "f"(y)); return r;
}
__device__ __forceinline__ ull fma2(ull a, ull b, ull c) {
    ull d; asm("fma.rn.f32x2 %0, %1, %2, %3;" : "=l"(d) : "l"(a), "l"(b), "l"(c));
    return d;
}
__device__ __forceinline__ void unpack2(ull v, float& lo, float& hi) {
    asm("mov.b64 {%0, %1}, %2;" : "=f"(lo), "=f"(hi) : "l"(v));
}

// ---------------- mma.sync helpers ---------------------------------------------
__device__ __forceinline__ uint32_t smem_u32(const void* p) {
    uint32_t a;
    asm("{ .reg .u64 t; cvta.to.shared.u64 t, %1; cvt.u32.u64 %0, t; }" : "=r"(a) : "l"(p));
    return a;
}
__device__ __forceinline__ uint32_t swz_addr(uint32_t base, int r, int cb) {
    uint32_t off = (uint32_t)(r * 128 + cb);
    off ^= (off >> 3) & 0x70;
    return base + off;
}
__device__ __forceinline__ void ldsm4(uint32_t& r0, uint32_t& r1, uint32_t& r2,
                                      uint32_t& r3, uint32_t addr) {
    asm volatile("ldmatrix.sync.aligned.m8n8.x4.shared.b16 {%0,%1,%2,%3}, [%4];"
                 : "=r"(r0), "=r"(r1), "=r"(r2), "=r"(r3) : "r"(addr));
}
__device__ __forceinline__ void mma16816(float* d, const uint32_t* a,
                                         uint32_t b0, uint32_t b1) {
    asm volatile(
        "mma.sync.aligned.m16n8k16.row.col.f32.bf16.bf16.f32 "
        "{%0,%1,%2,%3}, {%4,%5,%6,%7}, {%8,%9}, {%0,%1,%2,%3};"
        : "+f"(d[0]), "+f"(d[1]), "+f"(d[2]), "+f"(d[3])
        : "r"(a[0]), "r"(a[1]), "r"(a[2]), "r"(a[3]), "r"(b0), "r"(b1));
}
__device__ __forceinline__ void cpasync16(uint32_t dst, const void* src) {
    asm volatile("cp.async.cg.shared.global [%0], [%1], 16;" :: "r"(dst), "l"(src));
}

// ---------------- k0: weight permutation + splits --------------------------------
__global__ void kconv_w(const float* __restrict__ Wq, const float* __restrict__ Wp) {
    int i = blockIdx.x * 256 + threadIdx.x;    // 1024 blocks
    if (i < NQKV * DIMM) {
        int c = i >> 8, d = i & 255;
        int h = c / 96, t = c % 96, e = t / 3, s = t - e * 3;
        float v = Wq[i];
        if (s < 2) {
            g_wqk[(h * 64 + e * 2 + s) * DIMM + d] = v;
        } else {
            __nv_bfloat16 hh = __float2bfloat16(v);
            int idx = (h * 32 + e) * DIMM + d;
            g_wvh[idx] = hh;
            g_wvl[idx] = __float2bfloat16(v - __bfloat162float(hh));
        }
    } else {
        int j = i - NQKV * DIMM;
        float v = Wp[j];
        __nv_bfloat16 hh = __float2bfloat16(v);
        g_wph[j] = hh;
        g_wpl[j] = __float2bfloat16(v - __bfloat162float(hh));
    }
}

// ---------------- k1: PE add; write fp32 + bf16 splits ----------------------------
__global__ void k1_pe(const float* __restrict__ x, const float* __restrict__ pos,
                      const float* __restrict__ Wpe, const float* __restrict__ bpe) {
    int ball = blockIdx.x;
    int tid  = threadIdx.x;
    __shared__ float rel[MB][3];
    if (tid < 3) {
        float s = 0.f;
        for (int m = 0; m < MB; m++) s += pos[(ball * MB + m) * 3 + tid];
        float mean = s * (1.f / MB);
        for (int m = 0; m < MB; m++)
            rel[m][tid] = pos[(ball * MB + m) * 3 + tid] - mean;
    }
    __syncthreads();
    int d = tid;
    float w0 = Wpe[d * 3 + 0], w1 = Wpe[d * 3 + 1], w2 = Wpe[d * 3 + 2];
    float b  = bpe[d];
    #pragma unroll
    for (int m = 0; m < MB; m++) {
        int t = ball * MB + m;
        float v = x[t * DIMM + d]
                + rel[m][0] * w0 + rel[m][1] * w1 + rel[m][2] * w2 + b;
        g_xp[t * DIMM + d] = v;
        __nv_bfloat16 h = __float2bfloat16(v);
        g_xph[t * DIMM + d] = h;
        g_xpl[t * DIMM + d] = __float2bfloat16(v - __bfloat162float(h));
    }
}

// ---------------- fp32 f32x2 GEMM-NT for Q,K (N=512), reg-prefetch pipelined ------
__global__ void __launch_bounds__(256, 2)
k2_qk(const float* __restrict__ bias) {
    __shared__ float As[2][16 * 132];
    __shared__ float Bs[2][16 * 132];
    int tid = threadIdx.x;
    int tx = tid & 15, ty = tid >> 4;
    int row0 = blockIdx.x * 128, col0 = blockIdx.y * 128;
    int r  = tid & 127;
    int k8 = (tid >> 7) * 8;

    const float* Ap = g_xp  + (row0 + r) * DIMM + k8;
    const float* Bp = g_wqk + (col0 + r) * DIMM + k8;

    float4 pa0 = *(const float4*)(Ap);
    float4 pa1 = *(const float4*)(Ap + 4);
    float4 pb0 = *(const float4*)(Bp);
    float4 pb1 = *(const float4*)(Bp + 4);

    ull accp[8][4] = {};
    #pragma unroll 2
    for (int c = 0; c < 16; c++) {
        float* A = As[c & 1];
        float* B = Bs[c & 1];
        A[(k8 + 0) * 132 + r] = pa0.x; A[(k8 + 1) * 132 + r] = pa0.y;
        A[(k8 + 2) * 132 + r] = pa0.z; A[(k8 + 3) * 132 + r] = pa0.w;
        A[(k8 + 4) * 132 + r] = pa1.x; A[(k8 + 5) * 132 + r] = pa1.y;
        A[(k8 + 6) * 132 + r] = pa1.z; A[(k8 + 7) * 132 + r] = pa1.w;
        B[(k8 + 0) * 132 + r] = pb0.x; B[(k8 + 1) * 132 + r] = pb0.y;
        B[(k8 + 2) * 132 + r] = pb0.z; B[(k8 + 3) * 132 + r] = pb0.w;
        B[(k8 + 4) * 132 + r] = pb1.x; B[(k8 + 5) * 132 + r] = pb1.y;
        B[(k8 + 6) * 132 + r] = pb1.z; B[(k8 + 7) * 132 + r] = pb1.w;
        __syncthreads();
        if (c < 15) {
            int k0n = (c + 1) * 16;
            pa0 = *(const float4*)(Ap + k0n);
            pa1 = *(const float4*)(Ap + k0n + 4);
            pb0 = *(const float4*)(Bp + k0n);
            pb1 = *(const float4*)(Bp + k0n + 4);
        }
        #pragma unroll
        for (int kk = 0; kk < 16; kk++) {
            float4 a0 = *(const float4*)(A + kk * 132 + ty * 4);
            float4 a1 = *(const float4*)(A + kk * 132 + 64 + ty * 4);
            float4 b0 = *(const float4*)(B + kk * 132 + tx * 4);
            float4 b1 = *(const float4*)(B + kk * 132 + 64 + tx * 4);
            ull bp[4] = {pack2(b0.x, b0.y), pack2(b0.z, b0.w),
                         pack2(b1.x, b1.y), pack2(b1.z, b1.w)};
            float av[8] = {a0.x, a0.y, a0.z, a0.w, a1.x, a1.y, a1.z, a1.w};
            #pragma unroll
            for (int i = 0; i < 8; i++) {
                ull ap = pack2(av[i], av[i]);
                #pragma unroll
                for (int j = 0; j < 4; j++) accp[i][j] = fma2(ap, bp[j], accp[i][j]);
            }
        }
    }
    float acc[8][8];
    #pragma unroll
    for (int i = 0; i < 8; i++)
        #pragma unroll
        for (int j = 0; j < 4; j++)
            unpack2(accp[i][j], acc[i][2 * j], acc[i][2 * j + 1]);
    #pragma unroll
    for (int i = 0; i < 8; i++) {
        int rr = row0 + ((i < 4) ? ty * 4 + i : 64 + ty * 4 + i - 4);
        #pragma unroll
        for (int j = 0; j < 8; j++) {
            int cp = col0 + ((j < 4) ? tx * 4 + j : 64 + tx * 4 + j - 4);
            int h = cp >> 6, r6 = cp & 63;
            int e = r6 >> 1, s = r6 & 1;
            float v = acc[i][j] + bias[h * 96 + e * 3 + s];
            float* dst = (s == 0) ? g_q : g_k;
            dst[(h * NM + rr) * EE + e] = v;
        }
    }
}

// ---------------- split-bf16 HMMA GEMM-NT, cp.async pipelined ----------------------
// MODE 0: A=g_xph/l, B=g_wvh/l (N=256) -> g_v.  MODE 1: A=g_aoh/l, B=g_wph/l -> out.
template<int MODE>
__device__ __forceinline__ void issue_chunk(uint32_t stage, int row0, int col0,
                                            int k0, int tid) {
    const __nv_bfloat16* srcs[4] = {
        (MODE == 0) ? g_xph : g_aoh, (MODE == 0) ? g_xpl : g_aol,
        (MODE == 0) ? g_wvh : g_wph, (MODE == 0) ? g_wvl : g_wpl};
    #pragma unroll
    for (int b = 0; b < 4; b++) {
        int rbase = (b < 2) ? row0 : col0;
        #pragma unroll
        for (int l = 0; l < 4; l++) {
            int u = tid + l * 256;
            int r = u >> 3, cc = u & 7;
            const void* g = srcs[b] + (rbase + r) * DIMM + k0 + cc * 8;
            uint32_t off = (uint32_t)(r * 128 + cc * 16);
            off ^= (off >> 3) & 0x70;
            cpasync16(stage + b * 16384 + off, g);
        }
    }
    asm volatile("cp.async.commit_group;" ::: "memory");
}

template<int MODE>
__global__ void __launch_bounds__(256, 1)
gemm_mma(const float* __restrict__ bias, float* __restrict__ out) {
    extern __shared__ char dsm_raw[];
    int tid = threadIdx.x;
    int wid = tid >> 5, lane = tid & 31;
    int row0 = blockIdx.x * 128, col0 = blockIdx.y * 128;
    int warp_m = (wid & 1) * 64;
    int warp_n = (wid >> 1) * 32;

    uint32_t raw = smem_u32(dsm_raw);
    uint32_t sbase = (raw + 1023u) & ~1023u;

    float acc[4][4][4] = {};
    int lr = lane & 7;
    int g  = lane >> 3;

    issue_chunk<MODE>(sbase, row0, col0, 0, tid);

    for (int chunk = 0; chunk < 4; chunk++) {
        if (chunk < 3)
            issue_chunk<MODE>(sbase + ((chunk + 1) & 1) * 65536,
                              row0, col0, (chunk + 1) * 64, tid);
        if (chunk < 3)
            asm volatile("cp.async.wait_group 1;" ::: "memory");
        else
            asm volatile("cp.async.wait_group 0;" ::: "memory");
        __syncthreads();

        uint32_t st = sbase + (chunk & 1) * 65536;
        uint32_t aBuf[2] = {st, st + 16384};
        uint32_t bBuf[2] = {st + 32768, st + 49152};

        #pragma unroll
        for (int pass = 0; pass < 3; pass++) {
            uint32_t abase = aBuf[(pass == 2) ? 1 : 0];
            uint32_t bbase = bBuf[(pass == 1) ? 1 : 0];
            #pragma unroll
            for (int ks = 0; ks < 4; ks++) {
                uint32_t af[4][4];
                #pragma unroll
                for (int mi = 0; mi < 4; mi++) {
                    int row = warp_m + mi * 16 + ((g & 1) << 3) + lr;
                    int cb  = ks * 32 + ((g >> 1) << 4);
                    ldsm4(af[mi][0], af[mi][1], af[mi][2], af[mi][3],
                          swz_addr(abase, row, cb));
                }
                uint32_t bf[4][2];
                #pragma unroll
                for (int p = 0; p < 2; p++) {
                    int n  = warp_n + p * 16 + ((g >> 1) << 3) + lr;
                    int cb = ks * 32 + ((g & 1) << 4);
                    uint32_t r0, r1, r2, r3;
                    ldsm4(r0, r1, r2, r3, swz_addr(bbase, n, cb));
                    bf[p * 2 + 0][0] = r0; bf[p * 2 + 0][1] = r1;
                    bf[p * 2 + 1][0] = r2; bf[p * 2 + 1][1] = r3;
                }
                #pragma unroll
                for (int mi = 0; mi < 4; mi++)
                    #pragma unroll
                    for (int nj = 0; nj < 4; nj++)
                        mma16816(acc[mi][nj], af[mi], bf[nj][0], bf[nj][1]);
            }
        }
        __syncthreads();
    }

    int erow = lane >> 2;
    int ecol = (lane & 3) * 2;
    #pragma unroll
    for (int mi = 0; mi < 4; mi++) {
        #pragma unroll
        for (int nj = 0; nj < 4; nj++) {
            #pragma unroll
            for (int half = 0; half < 2; half++) {
                int r = row0 + warp_m + mi * 16 + erow + half * 8;
                #pragma unroll
                for (int rg = 0; rg < 2; rg++) {
                    int cp = col0 + warp_n + nj * 8 + ecol + rg;
                    if (MODE == 0) {
                        int h = cp >> 5, e = cp & 31;
                        float v = acc[mi][nj][half * 2 + rg] + bias[h * 96 + e * 3 + 2];
                        g_v[(h * NM + r) * EE + e] = v;
                    } else {
                        float v = acc[mi][nj][half * 2 + rg] + bias[cp];
                        out[r * DIMM + cp] = v;
                    }
                }
            }
        }
    }
}

// ---------------- k3: per-ball key means --------------------------------------------
__global__ void k3_kmean() {
    int t = blockIdx.x * blockDim.x + threadIdx.x;
    int e = t & 31;
    int ball = (t >> 5) & (NB - 1);
    int h = t >> 14;
    const float* base = g_k + (h * NM + ball * MB) * EE + e;
    float s = 0.f;
    #pragma unroll
    for (int m = 0; m < MB; m++) s += base[m * EE];
    g_kmean[t] = s * (1.f / MB);
}

// ---------------- k4: sim GEMM + in-register top-2 ----------------------------------
__global__ void __launch_bounds__(256)
k4_top2() {
    __shared__ float As[32 * 132];
    __shared__ float Bs[32 * 132];
    int h = blockIdx.y;
    int tok0 = blockIdx.x * 128;
    int tid = threadIdx.x;
    int tx = tid & 15, ty = tid >> 4;

    #pragma unroll
    for (int l = 0; l < 4; l++) {
        int i = tid + l * 256;
        int t = i >> 3;
        int e4 = i & 7;
        float4 v = *(const float4*)(g_q + (h * NM + tok0 + t) * EE + e4 * 4);
        As[(e4 * 4 + 0) * 132 + t] = v.x;
        As[(e4 * 4 + 1) * 132 + t] = v.y;
        As[(e4 * 4 + 2) * 132 + t] = v.z;
        As[(e4 * 4 + 3) * 132 + t] = v.w;
    }

    float v1[8], v2[8];
    int   i1[8], i2[8];
    #pragma unroll
    for (int i = 0; i < 8; i++) { v1[i] = -1e30f; v2[i] = -1e30f; i1[i] = 0; i2[i] = 0; }

    for (int tile = 0; tile < 4; tile++) {
        int ball0 = tile * 128;
        __syncthreads();
        #pragma unroll
        for (int l = 0; l < 4; l++) {
            int i = tid + l * 256;
            int b = i >> 3;
            int e4 = i & 7;
            float4 v = *(const float4*)(g_kmean + (h * NB + ball0 + b) * EE + e4 * 4);
            Bs[(e4 * 4 + 0) * 132 + b] = v.x;
            Bs[(e4 * 4 + 1) * 132 + b] = v.y;
            Bs[(e4 * 4 + 2) * 132 + b] = v.z;
            Bs[(e4 * 4 + 3) * 132 + b] = v.w;
        }
        __syncthreads();

        ull accp[8][4] = {};
        #pragma unroll
        for (int kk = 0; kk < 32; kk++) {
            float4 a0 = *(const float4*)(As + kk * 132 + ty * 4);
            float4 a1 = *(const float4*)(As + kk * 132 + 64 + ty * 4);
            float4 b0 = *(const float4*)(Bs + kk * 132 + tx * 4);
            float4 b1 = *(const float4*)(Bs + kk * 132 + 64 + tx * 4);
            ull bp[4] = {pack2(b0.x, b0.y), pack2(b0.z, b0.w),
                         pack2(b1.x, b1.y), pack2(b1.z, b1.w)};
            float av[8] = {a0.x, a0.y, a0.z, a0.w, a1.x, a1.y, a1.z, a1.w};
            #pragma unroll
            for (int i = 0; i < 8; i++) {
                ull ap = pack2(av[i], av[i]);
                #pragma unroll
                for (int j = 0; j < 4; j++) accp[i][j] = fma2(ap, bp[j], accp[i][j]);
            }
        }

        #pragma unroll
        for (int i = 0; i < 8; i++) {
            #pragma unroll
            for (int j = 0; j < 4; j++) {
                float slo, shi;
                unpack2(accp[i][j], slo, shi);
                int cbase = (j < 2) ? tx * 4 + j * 2 : 64 + tx * 4 + (j - 2) * 2;
                int blo = ball0 + cbase;
                int bhi = blo + 1;
                if (slo > v1[i]) { v2[i] = v1[i]; i2[i] = i1[i]; v1[i] = slo; i1[i] = blo; }
                else if (slo > v2[i]) { v2[i] = slo; i2[i] = blo; }
                if (shi > v1[i]) { v2[i] = v1[i]; i2[i] = i1[i]; v1[i] = shi; i1[i] = bhi; }
                else if (shi > v2[i]) { v2[i] = shi; i2[i] = bhi; }
            }
        }
    }

    #pragma unroll
    for (int i = 0; i < 8; i++) {
        float a1v = v1[i], a2v = v2[i];
        int   a1i = i1[i], a2i = i2[i];
        #pragma unroll
        for (int m = 1; m < 16; m <<= 1) {
            float o1v = __shfl_xor_sync(0xffffffffu, a1v, m);
            float o2v = __shfl_xor_sync(0xffffffffu, a2v, m);
            int   o1i = __shfl_xor_sync(0xffffffffu, a1i, m);
            int   o2i = __shfl_xor_sync(0xffffffffu, a2i, m);
            if (o1v > a1v) {
                if (a1v > o2v) { a2v = a1v; a2i = a1i; }
                else           { a2v = o2v; a2i = o2i; }
                a1v = o1v; a1i = o1i;
            } else {
                if (o1v > a2v) { a2v = o1v; a2i = o1i; }
            }
        }
        if (tx == 0) {
            int tok = tok0 + ((i < 4) ? ty * 4 + i : 64 + ty * 4 + i - 4);
            g_idx[(h * NM + tok) * 2 + 0] = a1i;
            g_idx[(h * NM + tok) * 2 + 1] = a2i;
        }
    }
}

// ---------------- k5: gathered 32-key attention + bf16 split out --------------------
__global__ void k5_attn() {
    int warp = (blockIdx.x * blockDim.x + threadIdx.x) >> 5;
    int lane = threadIdx.x & 31;
    int h = warp >> 13;
    int tok = warp & (NM - 1);
    int b0 = g_idx[warp * 2 + 0];
    int b1 = g_idx[warp * 2 + 1];

    int ball = (lane < 16) ? b0 : b1;
    int ktok = ball * MB + (lane & 15);
    const float4* krow = (const float4*)(g_k + (h * NM + ktok) * EE);
    const float4* qrow = (const float4*)(g_q + (h * NM + tok) * EE);
    float logit = 0.f;
    #pragma unroll
    for (int e = 0; e < 8; e++) {
        float4 qv = qrow[e], kv = krow[e];
        logit += qv.x * kv.x + qv.y * kv.y + qv.z * kv.z + qv.w * kv.w;
    }
    logit *= 0.17677669529663688f;

    float m = logit;
    #pragma unroll
    for (int off = 16; off > 0; off >>= 1)
        m = fmaxf(m, __shfl_xor_sync(0xffffffffu, m, off));
    float p = __expf(logit - m);
    float s = p;
    #pragma unroll
    for (int off = 16; off > 0; off >>= 1)
        s += __shfl_xor_sync(0xffffffffu, s, off);
    float attn = p / s;

    float out = 0.f;
    #pragma unroll
    for (int kk = 0; kk < NKEY; kk++) {
        float a = __shfl_sync(0xffffffffu, attn, kk);
        int kt = ((kk < 16) ? b0 : b1) * MB + (kk & 15);
        out += a * g_v[(h * NM + kt) * EE + lane];
    }
    int oi = tok * DIMM + h * EE + lane;
    __nv_bfloat16 hi = __float2bfloat16(out);
    g_aoh[oi] = hi;
    g_aol[oi] = __float2bfloat16(out - __bfloat162float(hi));
}

// ---------------- launch --------------------------------------------------------------
extern "C" void kernel_launch(void* const* d_in, const int* in_sizes, int n_in,
                              void* d_out, int out_size) {
    const float* x     = (const float*)d_in[0];
    const float* pos   = (const float*)d_in[1];
    const float* Wqkv  = (const float*)d_in[2];
    const float* bqkv  = (const float*)d_in[3];
    const float* Wpe   = (const float*)d_in[4];
    const float* bpe   = (const float*)d_in[5];
    const float* Wproj = (const float*)d_in[6];
    const float* bproj = (const float*)d_in[7];
    float* out = (float*)d_out;

    const int DSMEM = 2 * 65536 + 1024;
    cudaFuncSetAttribute(gemm_mma<0>, cudaFuncAttributeMaxDynamicSharedMemorySize, DSMEM);
    cudaFuncSetAttribute(gemm_mma<1>, cudaFuncAttributeMaxDynamicSharedMemorySize, DSMEM);

    kconv_w<<<1024, 256>>>(Wqkv, Wproj);
    k1_pe<<<NB, 256>>>(x, pos, Wpe, bpe);
    k2_qk<<<dim3(NM / 128, 512 / 128), 256>>>(bqkv);
    gemm_mma<0><<<dim3(NM / 128, 256 / 128), 256, DSMEM>>>(bqkv, nullptr);
    k3_kmean<<<(NH * NB * EE) / 256, 256>>>();
    k4_top2<<<dim3(NM / 128, NH), 256>>>();
    k5_attn<<<(NH * NM * 32) / 256, 256>>>();
    gemm_mma<1><<<dim3(NM / 128, DIMM / 128), 256, DSMEM>>>(bproj, out);
}